// round 17
// baseline (speedup 1.0000x reference)
#include <cuda_runtime.h>
#include <cuda_fp16.h>
#include <cstdint>

#define DEVINL __device__ __forceinline__

static constexpr int B_ROWS = 131072;
static constexpr int DIM    = 256;
static constexpr int C_COLS = 1000;
static constexpr int C_PAD  = 1024;

// CTA 128x128, 8 warps as 2(M) x 4(N) -> warp tile 64x32, int8 MMA, s32 acc
static constexpr int TILE_M   = 128;
static constexpr int TILE_N   = 128;
static constexpr int K_CHUNK  = 64;                    // int8 -> 64B smem rows (SW64)
static constexpr int N_CHUNKS = DIM / K_CHUNK;         // 4
static constexpr int N_STAGES = 4;
static constexpr int STAGE_A  = TILE_M * K_CHUNK;      // 8192
static constexpr int STAGE_B  = TILE_N * K_CHUNK;      // 8192
static constexpr int STAGE_BYTES = STAGE_A + STAGE_B;  // 16384
static constexpr int SMEM_REQ = N_STAGES * STAGE_BYTES; // 65536 -> 2 CTAs/SM

// scratch: per-row-max int8 quantized rows + per-row (norm-folded) scales
__device__ int8_t g_xq[(size_t)B_ROWS * DIM];
__device__ int8_t g_wq[(size_t)C_PAD * DIM];
__device__ float  g_sx[B_ROWS];   // sa = amax/(127*||row||)  (0 for invalid)
__device__ float  g_sc[C_PAD];    // sb

// ---------------- helpers ----------------
DEVINL uint32_t smem_u32(const void* p) {
    uint32_t a;
    asm("{ .reg .u64 t; cvta.to.shared.u64 t, %1; cvt.u32.u64 %0, t; }" : "=r"(a) : "l"(p));
    return a;
}
DEVINL void cp16(uint32_t dst, const void* src) {
    asm volatile("cp.async.cg.shared.global [%0], [%1], 16;" :: "r"(dst), "l"(src));
}
DEVINL void cp_commit() { asm volatile("cp.async.commit_group;" ::: "memory"); }
template <int N> DEVINL void cp_wait() {
    asm volatile("cp.async.wait_group %0;" :: "n"(N) : "memory");
}
DEVINL uint32_t sw64(uint32_t off) { return off ^ ((off >> 3) & 0x30); }

#define LDSM_X4(r0, r1, r2, r3, addr)                                             \
    asm volatile("ldmatrix.sync.aligned.m8n8.x4.shared.b16 {%0,%1,%2,%3}, [%4];"  \
                 : "=r"(r0), "=r"(r1), "=r"(r2), "=r"(r3) : "r"(addr))

// D(s32) += A(s8) * B(s8) : m16n8k32
DEVINL void mma16832_s8(int32_t* d, const uint32_t* a, const uint32_t* b) {
    asm volatile(
        "mma.sync.aligned.m16n8k32.row.col.s32.s8.s8.s32 "
        "{%0,%1,%2,%3}, {%4,%5,%6,%7}, {%8,%9}, {%0,%1,%2,%3};"
        : "+r"(d[0]), "+r"(d[1]), "+r"(d[2]), "+r"(d[3])
        : "r"(a[0]), "r"(a[1]), "r"(a[2]), "r"(a[3]), "r"(b[0]), "r"(b[1]));
}

// ---------------- prep: 2 rows/warp, fp32 -> per-row-max int8 + scale ----------
DEVINL float max8(const float4& v0, const float4& v1) {
    float m = fabsf(v0.x);
    m = fmaxf(m, fabsf(v0.y)); m = fmaxf(m, fabsf(v0.z)); m = fmaxf(m, fabsf(v0.w));
    m = fmaxf(m, fabsf(v1.x)); m = fmaxf(m, fabsf(v1.y));
    m = fmaxf(m, fabsf(v1.z)); m = fmaxf(m, fabsf(v1.w));
    return m;
}
DEVINL uint32_t pack4(float a, float b, float c, float d, float k) {
    int q0 = (int)rintf(a * k), q1 = (int)rintf(b * k);
    int q2 = (int)rintf(c * k), q3 = (int)rintf(d * k);
    return (uint32_t)(q0 & 255) | ((uint32_t)(q1 & 255) << 8) |
           ((uint32_t)(q2 & 255) << 16) | ((uint32_t)(q3 & 255) << 24);
}

DEVINL void prep_row_store(int8_t* dstq, float* dsts, int row, int lane,
                           const float4& v0, const float4& v1, bool ok) {
    uint32_t* drow = reinterpret_cast<uint32_t*>(dstq + (size_t)row * DIM);
    if (ok) {
        float s = v0.x * v0.x + v0.y * v0.y + v0.z * v0.z + v0.w * v0.w
                + v1.x * v1.x + v1.y * v1.y + v1.z * v1.z + v1.w * v1.w;
        float m = max8(v0, v1);
#pragma unroll
        for (int o = 16; o; o >>= 1) {
            s += __shfl_xor_sync(0xFFFFFFFFu, s, o);
            m = fmaxf(m, __shfl_xor_sync(0xFFFFFFFFu, m, o));
        }
        float k = (m > 0.0f) ? 127.0f / m : 0.0f;   // quantize raw; norm folded into scale
        drow[lane]      = pack4(v0.x, v0.y, v0.z, v0.w, k);
        drow[lane + 32] = pack4(v1.x, v1.y, v1.z, v1.w, k);
        if (lane == 0) {
            float rn = rsqrtf(fmaxf(s, 1e-24f));
            dsts[row] = m * rn / 127.0f;            // dequant scale of the NORMALIZED row
        }
    } else {
        drow[lane]      = 0u;
        drow[lane + 32] = 0u;
        if (lane == 0) dsts[row] = 0.0f;
    }
}

__global__ void prep_kernel(const float* __restrict__ x, const float* __restrict__ w,
                            float* __restrict__ wout) {
    int wp   = (blockIdx.x * blockDim.x + threadIdx.x) >> 5;
    int lane = threadIdx.x & 31;

    const float* src;
    int8_t* dstq;
    float* dsts;
    int row0, valid;
    bool isw;
    if (wp < C_PAD / 2) {
        src = w; dstq = g_wq; dsts = g_sc; row0 = wp * 2; valid = C_COLS; isw = true;
    } else {
        src = x; dstq = g_xq; dsts = g_sx; row0 = (wp - C_PAD / 2) * 2;
        valid = B_ROWS; isw = false;
        if (row0 >= B_ROWS) return;
    }
    bool ok0 = row0 < valid;
    bool ok1 = row0 + 1 < valid;

    float4 a0 = {}, a1 = {}, b0 = {}, b1 = {};
    const float4* p0 = reinterpret_cast<const float4*>(src + (size_t)row0 * DIM);
    const float4* p1 = reinterpret_cast<const float4*>(src + (size_t)(row0 + 1) * DIM);
    if (ok0) { a0 = p0[lane]; a1 = p0[lane + 32]; }
    if (ok1) { b0 = p1[lane]; b1 = p1[lane + 32]; }

    prep_row_store(dstq, dsts, row0,     lane, a0, a1, ok0);
    prep_row_store(dstq, dsts, row0 + 1, lane, b0, b1, ok1);

    if (isw && wout != nullptr) {
        if (ok0) {
            float4* o = reinterpret_cast<float4*>(wout + (size_t)row0 * DIM);
            o[lane] = a0; o[lane + 32] = a1;
        }
        if (ok1) {
            float4* o = reinterpret_cast<float4*>(wout + (size_t)(row0 + 1) * DIM);
            o[lane] = b0; o[lane + 32] = b1;
        }
    }
}

// ---------------- GEMM ----------------
DEVINL void load_chunk(uint32_t stage, int m0, int n0, int k0, int tid) {
    const int8_t* xa = g_xq + (size_t)m0 * DIM + k0;
    const int8_t* wb = g_wq + (size_t)n0 * DIM + k0;
    uint32_t sA = stage;
    uint32_t sB = stage + STAGE_A;
    // A: 128 rows x 4 x 16B (512 units), 2 iters
#pragma unroll
    for (int i = 0; i < 2; i++) {
        int g = tid + i * 256;
        int row = g >> 2, c = g & 3;
        cp16(sA + sw64((uint32_t)(row * 64 + c * 16)), xa + row * DIM + c * 16);
    }
    // B: 128 rows x 4 x 16B
#pragma unroll
    for (int i = 0; i < 2; i++) {
        int g = tid + i * 256;
        int row = g >> 2, c = g & 3;
        cp16(sB + sw64((uint32_t)(row * 64 + c * 16)), wb + row * DIM + c * 16);
    }
}

__global__ __launch_bounds__(256, 2)
void gemm_kernel(float* __restrict__ out) {
    extern __shared__ char smem[];
    uint32_t s0 = smem_u32(smem);

    int tid  = threadIdx.x;
    int wid  = tid >> 5;
    int lane = tid & 31;
    int bid  = blockIdx.x;
    int m0 = (bid >> 3) * TILE_M;
    int n0 = (bid & 7) * TILE_N;

    // prologue: chunks 0..2
    load_chunk(s0 + 0 * STAGE_BYTES, m0, n0, 0 * K_CHUNK, tid); cp_commit();
    load_chunk(s0 + 1 * STAGE_BYTES, m0, n0, 1 * K_CHUNK, tid); cp_commit();
    load_chunk(s0 + 2 * STAGE_BYTES, m0, n0, 2 * K_CHUNK, tid); cp_commit();

    int32_t acc[4][4][4];
#pragma unroll
    for (int i = 0; i < 4; i++)
#pragma unroll
        for (int j = 0; j < 4; j++)
#pragma unroll
            for (int k = 0; k < 4; k++) acc[i][j][k] = 0;

    int warp_m = wid >> 2;       // 0..1  -> 64 rows
    int warp_n = wid & 3;        // 0..3  -> 32 cols

    // tile address pattern: lanes 0-7 rows0-7@k0 | 8-15 rows0-7@k16 | 16-23 rows8-15@k0 | 24-31 rows8-15@k16
    int t_row = (lane & 7) + ((lane & 16) >> 1);   // 0..15 within 16-row block
    int t_kb  = (lane & 8) << 1;                   // 0 or 16 bytes

    int a_row = warp_m * 64 + t_row;
    int b_row = warp_n * 32 + t_row;

#pragma unroll 1
    for (int c = 0; c < N_CHUNKS; c++) {
        if      (c <= 1) cp_wait<2>();
        else if (c == 2) cp_wait<1>();
        else             cp_wait<0>();
        __syncthreads();

        if (c + 3 < N_CHUNKS) {
            load_chunk(s0 + ((c + 3) % N_STAGES) * STAGE_BYTES,
                       m0, n0, (c + 3) * K_CHUNK, tid);
            cp_commit();
        }

        uint32_t sA = s0 + (c % N_STAGES) * STAGE_BYTES;
        uint32_t sB = sA + STAGE_A;
#pragma unroll
        for (int ks = 0; ks < 2; ks++) {
            int kb = ks * 32 + t_kb;
            uint32_t a[4][4];
#pragma unroll
            for (int bm = 0; bm < 4; bm++) {
                int row = a_row + bm * 16;
                // tiles arrive as {r0-7k0, r0-7k16, r8-15k0, r8-15k16};
                // s8 A fragment wants {r0-7k0, r8-15k0, r0-7k16, r8-15k16} -> permute dests
                LDSM_X4(a[bm][0], a[bm][2], a[bm][1], a[bm][3],
                        sA + sw64((uint32_t)(row * 64 + kb)));
            }
            uint32_t b[2][4];   // each x4 covers 16 n-rows = 2 n8 blocks, pairs {k0,k16}
#pragma unroll
            for (int bb = 0; bb < 2; bb++) {
                int row = b_row + bb * 16;
                LDSM_X4(b[bb][0], b[bb][1], b[bb][2], b[bb][3],
                        sB + sw64((uint32_t)(row * 64 + kb)));
            }
#pragma unroll
            for (int bm = 0; bm < 4; bm++)
#pragma unroll
                for (int bb = 0; bb < 2; bb++) {
                    mma16832_s8(acc[bm][2 * bb],     a[bm], &b[bb][0]);
                    mma16832_s8(acc[bm][2 * bb + 1], a[bm], &b[bb][2]);
                }
        }
    }

    // ---------------- epilogue: logits = min(2*sa*sb*acc - 2, 0) ----------------
#pragma unroll
    for (int bm = 0; bm < 4; bm++) {
        int ma = m0 + warp_m * 64 + bm * 16 + (lane >> 2);
        int mb = ma + 8;
        float sa2 = 2.0f * g_sx[ma];
        float sb2 = 2.0f * g_sx[mb];
        float* rowa = out + (size_t)ma * C_COLS;
        float* rowb = out + (size_t)mb * C_COLS;
#pragma unroll
        for (int bn = 0; bn < 4; bn++) {
            int col = n0 + warp_n * 32 + bn * 8 + (lane & 3) * 2;
            if (col < C_COLS) {
                float sc0 = g_sc[col];
                float sc1 = g_sc[col + 1];
                float2 va, vb;
                va.x = fminf(fmaf(sa2 * sc0, (float)acc[bm][bn][0], -2.0f), 0.0f);
                va.y = fminf(fmaf(sa2 * sc1, (float)acc[bm][bn][1], -2.0f), 0.0f);
                vb.x = fminf(fmaf(sb2 * sc0, (float)acc[bm][bn][2], -2.0f), 0.0f);
                vb.y = fminf(fmaf(sb2 * sc1, (float)acc[bm][bn][3], -2.0f), 0.0f);
                *reinterpret_cast<float2*>(rowa + col) = va;
                *reinterpret_cast<float2*>(rowb + col) = vb;
            }
        }
    }
}

// ---------------- launch ----------------
extern "C" void kernel_launch(void* const* d_in, const int* in_sizes, int n_in,
                              void* d_out, int out_size) {
    const float* x = (const float*)d_in[0];
    const float* w = (const float*)d_in[1];
    float* out = (float*)d_out;

    cudaFuncSetAttribute(gemm_kernel, cudaFuncAttributeMaxDynamicSharedMemorySize, SMEM_REQ);

    long long logits_elems = (long long)B_ROWS * C_COLS;
    float* wout = nullptr;
    if ((long long)out_size >= logits_elems + (long long)C_COLS * DIM)
        wout = out + logits_elems;

    {
        int total_warps = C_PAD / 2 + B_ROWS / 2;      // 66048
        int blocks = (total_warps * 32 + 255) / 256;   // 8256
        prep_kernel<<<blocks, 256>>>(x, w, wout);
    }

    // 1024 m-tiles x 8 n-tiles (n fastest for x L2 reuse)
    gemm_kernel<<<(B_ROWS / TILE_M) * 8, 256, SMEM_REQ>>>(out);
}